// round 7
// baseline (speedup 1.0000x reference)
#include <cuda_runtime.h>
#include <cstdint>

typedef unsigned long long ull;

#define BB       8
#define NPTS     8192
#define RM       8            // targets per thread (4 packed pairs)
#define NPAIR    4
#define NT       128          // preds per smem tile
#define NTHREADS 128
#define MCHUNK   (NTHREADS * RM)   // 1024 targets per block
#define MCHUNKS  (NPTS / MCHUNK)   // 8
#define NSPLIT   16
#define NCHUNK   (NPTS / NSPLIT)   // 512 preds per block

// ---- scratch (no allocations allowed) ----
__device__ float4   g_p4[BB * NPTS];      // (px,py,pz,|p|^2)
__device__ float4   g_t4[BB * NPTS];      // (tx,ty,tz,|t|^2)
__device__ unsigned g_rowmin[BB * NPTS];  // min over preds, per target (uint-ordered nonneg float)
__device__ unsigned g_colmin[BB * NPTS];  // min over targets, per pred

// ---- packed f32x2 helpers (sm_100a packed fp32: add/mul/fma ONLY — no min) ----
__device__ __forceinline__ ull pack2(float lo, float hi) {
    ull r;
    asm("mov.b64 %0, {%1, %2};" : "=l"(r) : "f"(lo), "f"(hi));
    return r;
}
__device__ __forceinline__ void unpack2(ull v, float& lo, float& hi) {
    asm("mov.b64 {%0, %1}, %2;" : "=f"(lo), "=f"(hi) : "l"(v));
}
#define FMA2(d, a, b, c) asm("fma.rn.f32x2 %0, %1, %2, %3;" : "=l"(d) : "l"(a), "l"(b), "l"(c))
#define ADD2(d, a, b)    asm("add.rn.f32x2 %0, %1, %2;"     : "=l"(d) : "l"(a), "l"(b))

__device__ __forceinline__ unsigned redux_min_u32(unsigned v) {
    unsigned r;
    asm volatile("redux.sync.min.u32 %0, %1, 0xffffffff;" : "=r"(r) : "r"(v));
    return r;
}

// ---- pack inputs, compute squared norms, init mins ----
__global__ void prep_kernel(const float* __restrict__ pred, const float* __restrict__ targ) {
    int idx = blockIdx.x * blockDim.x + threadIdx.x;
    if (idx >= BB * NPTS) return;
    float px = pred[3 * idx + 0], py = pred[3 * idx + 1], pz = pred[3 * idx + 2];
    g_p4[idx] = make_float4(px, py, pz, px * px + py * py + pz * pz);
    float tx = targ[3 * idx + 0], ty = targ[3 * idx + 1], tz = targ[3 * idx + 2];
    g_t4[idx] = make_float4(tx, ty, tz, tx * tx + ty * ty + tz * tz);
    g_rowmin[idx] = 0x7F800000u;  // +inf
    g_colmin[idx] = 0x7F800000u;
}

// ---- fused distance + dual-min kernel (target-packed / pred-splat) ----
// Thread owns 8 targets packed as 4 f32x2 pairs (targets k*128+tid and
// (k+4)*128+tid) -> constants are 16 ull = 32 regs (half of the splat scheme).
// Pred tile stores each component DUPLICATED so LDS.64 at [2j] yields the
// splat (px,px) for free. Per j: 8 distances via 16 packed ops, row-mins as
// scalars, col-min = 7-FMNMX tree + redux.sync across lanes -> lane0 RED.
__global__ void __launch_bounds__(NTHREADS, 7) chamfer_main() {
    const int b = blockIdx.z, mc = blockIdx.y, ns = blockIdx.x;
    const int tid = threadIdx.x, lane = tid & 31;

    const float4* __restrict__ P = g_p4 + b * NPTS + ns * NCHUNK;
    const float4* __restrict__ T = g_t4 + b * NPTS + mc * MCHUNK;

    // dist = (p2 + t2) + (-2tx)*px + (-2ty)*py + (-2tz)*pz
    // pair p packs targets rows (p, p+4): ax pair = (-2tx_a, -2tx_b), etc.
    ull axq[NPAIR], ayq[NPAIR], azq[NPAIR], t2q[NPAIR];
#pragma unroll
    for (int p = 0; p < NPAIR; p++) {
        float4 ta = T[p * NTHREADS + tid];
        float4 tb = T[(p + 4) * NTHREADS + tid];
        axq[p] = pack2(-2.0f * ta.x, -2.0f * tb.x);
        ayq[p] = pack2(-2.0f * ta.y, -2.0f * tb.y);
        azq[p] = pack2(-2.0f * ta.z, -2.0f * tb.z);
        t2q[p] = pack2(ta.w, tb.w);
    }
    float rmin_a[NPAIR], rmin_b[NPAIR];
#pragma unroll
    for (int p = 0; p < NPAIR; p++) { rmin_a[p] = INFINITY; rmin_b[p] = INFINITY; }

    // duplicated pred tile: slots [2i],[2i+1] both hold pred i's component
    __shared__ __align__(16) float s_px[2 * NT], s_py[2 * NT], s_pz[2 * NT], s_pw[2 * NT];

    unsigned* __restrict__ colmin = g_colmin + b * NPTS + ns * NCHUNK;

    for (int t0 = 0; t0 < NCHUNK; t0 += NT) {
        __syncthreads();
        {
            float4 p = P[t0 + tid];  // one pred per thread per tile
            *(ull*)&s_px[2 * tid] = pack2(p.x, p.x);
            *(ull*)&s_py[2 * tid] = pack2(p.y, p.y);
            *(ull*)&s_pz[2 * tid] = pack2(p.z, p.z);
            *(ull*)&s_pw[2 * tid] = pack2(p.w, p.w);
        }
        __syncthreads();

#pragma unroll 8
        for (int j = 0; j < NT; j++) {
            // broadcast splat loads, immediate offsets (conflict-free LDS.64)
            ull px2 = *(const ull*)&s_px[2 * j];
            ull py2 = *(const ull*)&s_py[2 * j];
            ull pz2 = *(const ull*)&s_pz[2 * j];
            ull pw2 = *(const ull*)&s_pw[2 * j];
            float da[NPAIR], db[NPAIR];
#pragma unroll
            for (int p = 0; p < NPAIR; p++) {
                ull acc;
                ADD2(acc, pw2, t2q[p]);          // (pw+t2_a, pw+t2_b)
                FMA2(acc, azq[p], pz2, acc);
                FMA2(acc, ayq[p], py2, acc);
                FMA2(acc, axq[p], px2, acc);
                unpack2(acc, da[p], db[p]);      // register-pair renaming, no movs
                rmin_a[p] = fminf(rmin_a[p], da[p]);
                rmin_b[p] = fminf(rmin_b[p], db[p]);
            }
            // col-min tree over this thread's 8 targets (7 FMNMX)
            float c = fminf(fminf(fminf(da[0], db[0]), fminf(da[1], db[1])),
                            fminf(fminf(da[2], db[2]), fminf(da[3], db[3])));
            // cross-lane min over warp's 256 targets; clamp >=0 keeps uint order
            unsigned wmin = redux_min_u32(__float_as_uint(fmaxf(c, 0.0f)));
            if (lane == 0) atomicMin(&colmin[t0 + j], wmin);
        }
    }

#pragma unroll
    for (int p = 0; p < NPAIR; p++) {
        float va = fmaxf(rmin_a[p], 0.0f);
        float vb = fmaxf(rmin_b[p], 0.0f);
        atomicMin(&g_rowmin[b * NPTS + mc * MCHUNK + p * NTHREADS + tid],
                  __float_as_uint(va));
        atomicMin(&g_rowmin[b * NPTS + mc * MCHUNK + (p + 4) * NTHREADS + tid],
                  __float_as_uint(vb));
    }
}

// ---- final reduction: loss = mean(rowmin) + mean(colmin) ----
__global__ void reduce_kernel(float* __restrict__ out) {
    __shared__ float sh[32];
    int tid = threadIdx.x;
    float s = 0.f;
    for (int i = tid; i < BB * NPTS; i += 1024)
        s += __uint_as_float(g_rowmin[i]) + __uint_as_float(g_colmin[i]);
#pragma unroll
    for (int o = 16; o; o >>= 1) s += __shfl_down_sync(0xFFFFFFFFu, s, o);
    if ((tid & 31) == 0) sh[tid >> 5] = s;
    __syncthreads();
    if (tid < 32) {
        float v = sh[tid];
#pragma unroll
        for (int o = 16; o; o >>= 1) v += __shfl_down_sync(0xFFFFFFFFu, v, o);
        if (tid == 0) out[0] = v / (float)(BB * NPTS);
    }
}

extern "C" void kernel_launch(void* const* d_in, const int* in_sizes, int n_in,
                              void* d_out, int out_size) {
    const float* pred = (const float*)d_in[0];
    const float* targ = (const float*)d_in[1];
    prep_kernel<<<(BB * NPTS + 255) / 256, 256>>>(pred, targ);
    chamfer_main<<<dim3(NSPLIT, MCHUNKS, BB), NTHREADS>>>();
    reduce_kernel<<<1, 1024>>>((float*)d_out);
}

// round 8
// speedup vs baseline: 1.0666x; 1.0666x over previous
#include <cuda_runtime.h>
#include <cstdint>

typedef unsigned long long ull;

#define BB       8
#define NPTS     8192
#define RM       8
#define NT       128
#define NTHREADS 128
#define MCHUNK   (NTHREADS * RM)       // 1024 targets per (b,mc)
#define MCHUNKS  (NPTS / MCHUNK)       // 8
#define NTILES   (NPTS / NT)           // 64 pred tiles per (b,mc)
#define NUNITS   (BB * MCHUNKS * NTILES)  // 4096 work units
#define NWORKERS (148 * 4)             // 592 persistent blocks (one wave)

// ---- scratch (no allocations allowed) ----
__device__ float4   g_p4[BB * NPTS];      // (px,py,pz,|p|^2)
__device__ float4   g_t4[BB * NPTS];      // (tx,ty,tz,|t|^2)
__device__ unsigned g_rowmin[BB * NPTS];  // min over preds, per target (uint-ordered nonneg float)
__device__ unsigned g_colmin[BB * NPTS];  // min over targets, per pred

// ---- packed f32x2 helpers (sm_100a: add/mul/fma only; rt==scalar FLOP rate, saves issue) ----
__device__ __forceinline__ ull splat2(float v) {
    ull r;
    asm("mov.b64 %0, {%1, %2};" : "=l"(r) : "f"(v), "f"(v));
    return r;
}
__device__ __forceinline__ void unpack2(ull v, float& lo, float& hi) {
    asm("mov.b64 {%0, %1}, %2;" : "=f"(lo), "=f"(hi) : "l"(v));
}
#define FMA2(d, a, b, c) asm("fma.rn.f32x2 %0, %1, %2, %3;" : "=l"(d) : "l"(a), "l"(b), "l"(c))
#define ADD2(d, a, b)    asm("add.rn.f32x2 %0, %1, %2;"     : "=l"(d) : "l"(a), "l"(b))

__device__ __forceinline__ unsigned redux_min_u32(unsigned v) {
    unsigned r;
    asm volatile("redux.sync.min.u32 %0, %1, 0xffffffff;" : "=r"(r) : "r"(v));
    return r;
}

// ---- pack inputs, compute squared norms, init mins ----
__global__ void prep_kernel(const float* __restrict__ pred, const float* __restrict__ targ) {
    int idx = blockIdx.x * blockDim.x + threadIdx.x;
    if (idx >= BB * NPTS) return;
    float px = pred[3 * idx + 0], py = pred[3 * idx + 1], pz = pred[3 * idx + 2];
    g_p4[idx] = make_float4(px, py, pz, px * px + py * py + pz * pz);
    float tx = targ[3 * idx + 0], ty = targ[3 * idx + 1], tz = targ[3 * idx + 2];
    g_t4[idx] = make_float4(tx, ty, tz, tx * tx + ty * ty + tz * tz);
    g_rowmin[idx] = 0x7F800000u;  // +inf
    g_colmin[idx] = 0x7F800000u;
}

// ---- persistent fused distance + dual-min kernel ----
// 592 blocks (148 SMs x 4), grid-stride over 4096 units. Unit u:
//   b = u>>9, mc = (u>>6)&7, tile = u&63  (128 preds x 1024 targets).
// Per unit: reload 8 target constants (splat-packed, L2-hot), fill pred tile
// in pair-split smem layout (slots [2i],[2i+1] = preds i, i+64), then 64 j
// steps; each j computes 16 distances/thread via fma.rn.f32x2, row-mins in
// registers (flushed to global per unit), col-min via 7+7 FMNMX tree +
// redux.sync.min.u32 + lane0 atomicMin.
__global__ void __launch_bounds__(NTHREADS) chamfer_main() {
    const int tid = threadIdx.x, lane = tid & 31;

    __shared__ __align__(16) float s_px[NT], s_py[NT], s_pz[NT], s_pw[NT];

    for (int u = blockIdx.x; u < NUNITS; u += NWORKERS) {
        const int b = u >> 9, mc = (u >> 6) & 7, tl = u & 63;

        const float4* __restrict__ T = g_t4 + b * NPTS + mc * MCHUNK;
        const float4* __restrict__ P = g_p4 + b * NPTS + tl * NT;

        // splat-packed target constants: dist = (p2+t2) -2tx*px -2ty*py -2tz*pz
        ull axp[RM], ayp[RM], azp[RM], t2p[RM];
#pragma unroll
        for (int k = 0; k < RM; k++) {
            float4 t = T[k * NTHREADS + tid];
            axp[k] = splat2(-2.0f * t.x);
            ayp[k] = splat2(-2.0f * t.y);
            azp[k] = splat2(-2.0f * t.z);
            t2p[k] = splat2(t.w);
        }
        float rlo[RM], rhi[RM];
#pragma unroll
        for (int k = 0; k < RM; k++) { rlo[k] = INFINITY; rhi[k] = INFINITY; }

        __syncthreads();  // previous unit's j-loop done before tile overwrite
        {
            float4 p = P[tid];
            int i = tid & 63, h = tid >> 6;
            s_px[2 * i + h] = p.x;
            s_py[2 * i + h] = p.y;
            s_pz[2 * i + h] = p.z;
            s_pw[2 * i + h] = p.w;
        }
        __syncthreads();

        unsigned* __restrict__ colmin = g_colmin + b * NPTS + tl * NT;

#pragma unroll 8
        for (int j = 0; j < 64; j++) {
            // broadcast loads, immediate offsets (conflict-free LDS.64)
            ull pxp = *(const ull*)&s_px[2 * j];
            ull pyp = *(const ull*)&s_py[2 * j];
            ull pzp = *(const ull*)&s_pz[2 * j];
            ull pwp = *(const ull*)&s_pw[2 * j];
            float dlo[RM], dhi[RM];
#pragma unroll
            for (int k = 0; k < RM; k++) {
                ull acc;
                ADD2(acc, pwp, t2p[k]);
                FMA2(acc, azp[k], pzp, acc);
                FMA2(acc, ayp[k], pyp, acc);
                FMA2(acc, axp[k], pxp, acc);
                unpack2(acc, dlo[k], dhi[k]);   // register-pair renaming, no movs
                rlo[k] = fminf(rlo[k], dlo[k]);
                rhi[k] = fminf(rhi[k], dhi[k]);
            }
            // col-min trees over k (7 + 7 FMNMX)
            float clo = fminf(fminf(fminf(dlo[0], dlo[1]), fminf(dlo[2], dlo[3])),
                              fminf(fminf(dlo[4], dlo[5]), fminf(dlo[6], dlo[7])));
            float chi = fminf(fminf(fminf(dhi[0], dhi[1]), fminf(dhi[2], dhi[3])),
                              fminf(fminf(dhi[4], dhi[5]), fminf(dhi[6], dhi[7])));
            // cross-lane min (clamp >=0 keeps uint ordering exact), lane0 -> global
            unsigned wlo = redux_min_u32(__float_as_uint(fmaxf(clo, 0.0f)));
            unsigned whi = redux_min_u32(__float_as_uint(fmaxf(chi, 0.0f)));
            if (lane == 0) {
                atomicMin(&colmin[j], wlo);
                atomicMin(&colmin[j + 64], whi);
            }
        }

        // flush this unit's row mins
#pragma unroll
        for (int k = 0; k < RM; k++) {
            float v = fmaxf(fminf(rlo[k], rhi[k]), 0.0f);
            atomicMin(&g_rowmin[b * NPTS + mc * MCHUNK + k * NTHREADS + tid],
                      __float_as_uint(v));
        }
    }
}

// ---- final reduction: loss = mean(rowmin) + mean(colmin) ----
__global__ void reduce_kernel(float* __restrict__ out) {
    __shared__ float sh[32];
    int tid = threadIdx.x;
    float s = 0.f;
    for (int i = tid; i < BB * NPTS; i += 1024)
        s += __uint_as_float(g_rowmin[i]) + __uint_as_float(g_colmin[i]);
#pragma unroll
    for (int o = 16; o; o >>= 1) s += __shfl_down_sync(0xFFFFFFFFu, s, o);
    if ((tid & 31) == 0) sh[tid >> 5] = s;
    __syncthreads();
    if (tid < 32) {
        float v = sh[tid];
#pragma unroll
        for (int o = 16; o; o >>= 1) v += __shfl_down_sync(0xFFFFFFFFu, v, o);
        if (tid == 0) out[0] = v / (float)(BB * NPTS);
    }
}

extern "C" void kernel_launch(void* const* d_in, const int* in_sizes, int n_in,
                              void* d_out, int out_size) {
    const float* pred = (const float*)d_in[0];
    const float* targ = (const float*)d_in[1];
    prep_kernel<<<(BB * NPTS + 255) / 256, 256>>>(pred, targ);
    chamfer_main<<<NWORKERS, NTHREADS>>>();
    reduce_kernel<<<1, 1024>>>((float*)d_out);
}